// round 2
// baseline (speedup 1.0000x reference)
#include <cuda_runtime.h>
#include <math.h>

// ---------------------------------------------------------------------------
// GAT (GATConv-style) on GB300.
// Pipeline:
//   1. h = x @ W                      (fp32 GEMM, smem-tiled)
//   2. a_src/a_dst = <h, att_*>      (warp per node)
//   3. CSR-by-dst build: count -> scan -> fill (int atomics only)
//   4. warp-per-node segment softmax + weighted gather-aggregate + ELU
// Self loops are handled inline in step 4 (never stored in CSR).
// edge_index arrives as int32 (JAX x64 disabled downcasts int64 -> int32).
// ---------------------------------------------------------------------------

#define MAXN 100000
#define MAXE 1600000
#define HD   128      // HEADS * OUT_DIM
#define NHEADS 4
#define NEG_SLOPE 0.2f

// scratch (allocation-free rule: __device__ globals)
__device__ float g_h[MAXN * HD];          // 51.2 MB
__device__ float g_asrc[MAXN * NHEADS];
__device__ float g_adst[MAXN * NHEADS];
__device__ int   g_cnt[MAXN];
__device__ int   g_off[MAXN + 1];
__device__ int   g_cur[MAXN];
__device__ int   g_csr[MAXE];             // 6.4 MB
__device__ int   g_bsums[256];

// ---------------------------------------------------------------------------
// 1. GEMM: h[N,128] = x[N,128] @ W[128,128]
// Block = 128 threads, 64 rows/block. W (64KB) + x tile (32KB) in dyn smem.
// ---------------------------------------------------------------------------
__global__ void gemm_kernel(const float* __restrict__ x,
                            const float* __restrict__ W,
                            float* __restrict__ h, int N)
{
    extern __shared__ float sm[];
    float* Ws = sm;               // 128*128
    float* xs = sm + 128 * 128;   // 64*128

    const int tid = threadIdx.x;
    const int row0 = blockIdx.x * 64;

    for (int i = tid; i < 128 * 128; i += 128)
        Ws[i] = W[i];
    for (int i = tid; i < 64 * 128; i += 128) {
        int r = row0 + (i >> 7);
        xs[i] = (r < N) ? x[r * 128 + (i & 127)] : 0.0f;
    }
    __syncthreads();

    const int cg = tid & 31;   // column group: cols [cg*4, cg*4+4)
    const int rg = tid >> 5;   // row group within iteration

    for (int it = 0; it < 4; ++it) {
        int rb = it * 16 + rg * 4;  // local row base
        float acc[4][4];
        #pragma unroll
        for (int r = 0; r < 4; ++r)
            #pragma unroll
            for (int c = 0; c < 4; ++c) acc[r][c] = 0.0f;

        #pragma unroll 4
        for (int k = 0; k < 128; ++k) {
            float4 w = *(const float4*)&Ws[k * 128 + cg * 4];
            #pragma unroll
            for (int r = 0; r < 4; ++r) {
                float xv = xs[(rb + r) * 128 + k];
                acc[r][0] += xv * w.x;
                acc[r][1] += xv * w.y;
                acc[r][2] += xv * w.z;
                acc[r][3] += xv * w.w;
            }
        }
        #pragma unroll
        for (int r = 0; r < 4; ++r) {
            int row = row0 + rb + r;
            if (row < N) {
                float4 o = make_float4(acc[r][0], acc[r][1], acc[r][2], acc[r][3]);
                *(float4*)&h[row * 128 + cg * 4] = o;
            }
        }
    }
}

// ---------------------------------------------------------------------------
// 2. a_src[n,h] = sum_d h[n,h,d]*att_src[h,d]  (warp per node)
// ---------------------------------------------------------------------------
__global__ void att_kernel(const float* __restrict__ h,
                           const float* __restrict__ att_src,
                           const float* __restrict__ att_dst,
                           float* __restrict__ asrc,
                           float* __restrict__ adst, int N)
{
    int gtid = blockIdx.x * blockDim.x + threadIdx.x;
    int n = gtid >> 5;
    int lane = gtid & 31;
    if (n >= N) return;

    float4 v = *(const float4*)&h[n * 128 + lane * 4];
    int head = lane >> 3;
    int dbase = (lane & 7) * 4;
    float4 as = *(const float4*)&att_src[head * 32 + dbase];
    float4 ad = *(const float4*)&att_dst[head * 32 + dbase];

    float s = v.x * as.x + v.y * as.y + v.z * as.z + v.w * as.w;
    float d = v.x * ad.x + v.y * ad.y + v.z * ad.z + v.w * ad.w;
    #pragma unroll
    for (int o = 4; o; o >>= 1) {
        s += __shfl_xor_sync(0xffffffffu, s, o);
        d += __shfl_xor_sync(0xffffffffu, d, o);
    }
    if ((lane & 7) == 0) {
        asrc[n * 4 + head] = s;
        adst[n * 4 + head] = d;
    }
}

// ---------------------------------------------------------------------------
// 3a. count edges per dst  (edge_index is int32: src = ei[t], dst = ei[E+t])
// ---------------------------------------------------------------------------
__global__ void count_kernel(const int* __restrict__ ei, int E)
{
    int t = blockIdx.x * blockDim.x + threadIdx.x;
    if (t >= E) return;
    int dst = ei[E + t];
    atomicAdd(&g_cnt[dst], 1);
}

// 3b. chunk-wise exclusive scan (1024 elems/block) -> g_off, block sums
__global__ void scan1_kernel(int N)
{
    __shared__ int sh[1024];
    int tid = threadIdx.x;
    int i = blockIdx.x * 1024 + tid;
    int v = (i < N) ? g_cnt[i] : 0;
    sh[tid] = v;
    __syncthreads();
    #pragma unroll
    for (int off = 1; off < 1024; off <<= 1) {
        int t = (tid >= off) ? sh[tid - off] : 0;
        __syncthreads();
        sh[tid] += t;
        __syncthreads();
    }
    int inc = sh[tid];
    if (i < N) g_off[i] = inc - v;      // exclusive within chunk
    if (tid == 1023) g_bsums[blockIdx.x] = inc;
}

// 3c. scan the block sums (NB <= 128), single block of 128 threads
__global__ void scan2_kernel(int NB, int N)
{
    __shared__ int sh[128];
    int tid = threadIdx.x;
    int v = (tid < NB) ? g_bsums[tid] : 0;
    sh[tid] = v;
    __syncthreads();
    #pragma unroll
    for (int off = 1; off < 128; off <<= 1) {
        int t = (tid >= off) ? sh[tid - off] : 0;
        __syncthreads();
        sh[tid] += t;
        __syncthreads();
    }
    int inc = sh[tid];
    if (tid < NB) g_bsums[tid] = inc - v;   // exclusive
    if (tid == NB - 1) g_off[N] = inc;      // total edge count
}

// 3d. add block offsets, init fill cursors
__global__ void scan3_kernel(int N)
{
    int i = blockIdx.x * blockDim.x + threadIdx.x;
    if (i >= N) return;
    int o = g_off[i] + g_bsums[i >> 10];
    g_off[i] = o;
    g_cur[i] = o;
}

// 3e. scatter src ids into CSR
__global__ void fill_kernel(const int* __restrict__ ei, int E)
{
    int t = blockIdx.x * blockDim.x + threadIdx.x;
    if (t >= E) return;
    int src = ei[t];
    int dst = ei[E + t];
    int pos = atomicAdd(&g_cur[dst], 1);
    g_csr[pos] = src;
}

// ---------------------------------------------------------------------------
// 4. warp-per-node: segment softmax + weighted aggregate + ELU.
// ---------------------------------------------------------------------------
__device__ __forceinline__ float leaky(float x) {
    return x > 0.0f ? x : NEG_SLOPE * x;
}

__global__ void aggregate_kernel(const float* __restrict__ h,
                                 const float* __restrict__ asrc,
                                 const float* __restrict__ adst,
                                 const float* __restrict__ bias,
                                 float* __restrict__ out, int N)
{
    int gtid = blockIdx.x * blockDim.x + threadIdx.x;
    int n = gtid >> 5;
    int lane = gtid & 31;
    if (n >= N) return;

    int s0 = g_off[n];
    int s1 = g_off[n + 1];

    float4 adn4 = *(const float4*)&adst[n * 4];
    float4 asn4 = *(const float4*)&asrc[n * 4];
    float adh[4] = {adn4.x, adn4.y, adn4.z, adn4.w};
    float ash[4] = {asn4.x, asn4.y, asn4.z, asn4.w};

    // ---- pass 1: per-head max (init = self-loop logit) ----
    float mx[4];
    #pragma unroll
    for (int hh = 0; hh < 4; ++hh) mx[hh] = leaky(ash[hh] + adh[hh]);

    for (int e = s0 + lane; e < s1; e += 32) {
        int s = g_csr[e];
        float4 as = *(const float4*)&asrc[s * 4];
        mx[0] = fmaxf(mx[0], leaky(as.x + adh[0]));
        mx[1] = fmaxf(mx[1], leaky(as.y + adh[1]));
        mx[2] = fmaxf(mx[2], leaky(as.z + adh[2]));
        mx[3] = fmaxf(mx[3], leaky(as.w + adh[3]));
    }
    #pragma unroll
    for (int hh = 0; hh < 4; ++hh)
        #pragma unroll
        for (int o = 16; o; o >>= 1)
            mx[hh] = fmaxf(mx[hh], __shfl_xor_sync(0xffffffffu, mx[hh], o));

    // ---- pass 2: exp-weight + accumulate ----
    const int myhead = lane >> 3;
    const float admy = adh[myhead];
    const float mxmy = mx[myhead];

    // self loop
    float w_self = __expf(leaky(ash[myhead] + admy) - mxmy);
    float4 hv = *(const float4*)&h[n * 128 + lane * 4];
    float a0 = w_self * hv.x, a1 = w_self * hv.y;
    float a2 = w_self * hv.z, a3 = w_self * hv.w;
    float den = ((lane & 7) == 0) ? w_self : 0.0f;

    for (int e = s0; e < s1; ++e) {
        int s = g_csr[e];                              // uniform across warp
        float as_my = asrc[s * 4 + myhead];
        float w = __expf(leaky(as_my + admy) - mxmy);
        float4 v = *(const float4*)&h[s * 128 + lane * 4];
        a0 += w * v.x; a1 += w * v.y; a2 += w * v.z; a3 += w * v.w;
        if ((lane & 7) == 0) den += w;
    }

    float dtot = __shfl_sync(0xffffffffu, den, myhead * 8);
    float inv = 1.0f / (dtot + 1e-16f);

    float4 b4 = *(const float4*)&bias[lane * 4];
    float o0 = a0 * inv + b4.x;
    float o1 = a1 * inv + b4.y;
    float o2 = a2 * inv + b4.z;
    float o3 = a3 * inv + b4.w;
    // ELU (alpha = 1)
    o0 = o0 > 0.0f ? o0 : (__expf(o0) - 1.0f);
    o1 = o1 > 0.0f ? o1 : (__expf(o1) - 1.0f);
    o2 = o2 > 0.0f ? o2 : (__expf(o2) - 1.0f);
    o3 = o3 > 0.0f ? o3 : (__expf(o3) - 1.0f);
    *(float4*)&out[n * 128 + lane * 4] = make_float4(o0, o1, o2, o3);
}

// ---------------------------------------------------------------------------
extern "C" void kernel_launch(void* const* d_in, const int* in_sizes, int n_in,
                              void* d_out, int out_size)
{
    const float* x        = (const float*)d_in[0];
    const int*   ei       = (const int*)d_in[1];     // int32 edge_index [2, E]
    const float* W        = (const float*)d_in[2];
    const float* att_src  = (const float*)d_in[3];
    const float* att_dst  = (const float*)d_in[4];
    const float* bias     = (const float*)d_in[5];
    float*       out      = (float*)d_out;

    const int N = in_sizes[0] / 128;
    const int E = in_sizes[1] / 2;

    float *h_p, *asrc_p, *adst_p;
    int   *cnt_p;
    cudaGetSymbolAddress((void**)&h_p,    g_h);
    cudaGetSymbolAddress((void**)&asrc_p, g_asrc);
    cudaGetSymbolAddress((void**)&adst_p, g_adst);
    cudaGetSymbolAddress((void**)&cnt_p,  g_cnt);

    cudaFuncSetAttribute(gemm_kernel,
                         cudaFuncAttributeMaxDynamicSharedMemorySize, 98304);

    cudaMemsetAsync(cnt_p, 0, N * sizeof(int));

    gemm_kernel<<<(N + 63) / 64, 128, 98304>>>(x, W, h_p, N);
    att_kernel<<<(N * 32 + 255) / 256, 256>>>(h_p, att_src, att_dst,
                                              asrc_p, adst_p, N);
    count_kernel<<<(E + 255) / 256, 256>>>(ei, E);

    int NB = (N + 1023) / 1024;
    scan1_kernel<<<NB, 1024>>>(N);
    scan2_kernel<<<1, 128>>>(NB, N);
    scan3_kernel<<<(N + 255) / 256, 256>>>(N);
    fill_kernel<<<(E + 255) / 256, 256>>>(ei, E);

    aggregate_kernel<<<(N * 32 + 255) / 256, 256>>>(h_p, asrc_p, adst_p,
                                                    bias, out, N);
}

// round 4
// speedup vs baseline: 1.8042x; 1.8042x over previous
#include <cuda_runtime.h>
#include <math.h>
#include <stdint.h>

// ---------------------------------------------------------------------------
// GAT on GB300, round 3:
//  1. h = x@W via tf32 mma.sync (m16n8k8), att dots fused in epilogue
//  2. CSR-by-dst build (count -> scan -> fill)
//  3. warp-per-node single-pass softmax aggregate (no max subtraction;
//     logits are O(10), exp cannot overflow) + ELU
// ---------------------------------------------------------------------------

#define MAXN 100000
#define MAXE 1600000
#define NEG_SLOPE 0.2f

__device__ float g_h[MAXN * 128];         // 51.2 MB
__device__ float g_asrc[MAXN * 4];
__device__ float g_adst[MAXN * 4];
__device__ int   g_cnt[MAXN];
__device__ int   g_off[MAXN + 1];
__device__ int   g_cur[MAXN];
__device__ int   g_csr[MAXE];
__device__ int   g_bsums[256];

// ---------------------------------------------------------------------------
__device__ __forceinline__ float tf32r(float v) {
    uint32_t o;
    asm("cvt.rna.tf32.f32 %0, %1;" : "=r"(o) : "f"(v));
    return __uint_as_float(o);
}

__device__ __forceinline__ void mma_tf32(float c[4],
                                         uint32_t a0, uint32_t a1,
                                         uint32_t a2, uint32_t a3,
                                         uint32_t b0, uint32_t b1) {
    asm volatile(
        "mma.sync.aligned.m16n8k8.row.col.f32.tf32.tf32.f32 "
        "{%0,%1,%2,%3}, {%4,%5,%6,%7}, {%8,%9}, {%0,%1,%2,%3};\n"
        : "+f"(c[0]), "+f"(c[1]), "+f"(c[2]), "+f"(c[3])
        : "r"(a0), "r"(a1), "r"(a2), "r"(a3), "r"(b0), "r"(b1));
}

// ---------------------------------------------------------------------------
// GEMM + fused attention dots.
// Block: 256 threads (8 warps), 64 rows. smem: xs[64][132], wt[128][132],
// att vectors (256 floats). Warp w: m-tile (w&3) -> rows (w&3)*16..+16,
// n-half (w>>2) -> cols (w>>2)*64..+64.
// ---------------------------------------------------------------------------
__global__ void gemm_att_kernel(const float* __restrict__ x,
                                const float* __restrict__ W,
                                const float* __restrict__ att_src,
                                const float* __restrict__ att_dst,
                                float* __restrict__ h,
                                float* __restrict__ asrc,
                                float* __restrict__ adst, int N)
{
    extern __shared__ float sm[];
    float* xs    = sm;                  // 64*132
    float* wt    = sm + 64 * 132;       // 128*132 (W transposed: wt[n][k])
    float* attsm = wt + 128 * 132;      // [0:128) att_src, [128:256) att_dst

    const int tid  = threadIdx.x;
    const int row0 = blockIdx.x * 64;

    if (tid < 256)
        attsm[tid] = (tid < 128) ? att_src[tid] : att_dst[tid - 128];

    for (int i = tid; i < 64 * 128; i += 256) {
        int r = i >> 7, k = i & 127;
        int grow = row0 + r;
        float v = (grow < N) ? x[grow * 128 + k] : 0.0f;
        xs[r * 132 + k] = tf32r(v);
    }
    for (int i = tid; i < 128 * 128; i += 256) {
        int k = i >> 7, n = i & 127;
        wt[n * 132 + k] = tf32r(W[i]);
    }
    __syncthreads();

    const int warp = tid >> 5, lane = tid & 31;
    const int mt = warp & 3;       // rows mt*16 .. +16
    const int nh = warp >> 2;      // cols nh*64 .. +64
    const int g = lane >> 2, t = lane & 3;

    float acc[8][4];
    #pragma unroll
    for (int i = 0; i < 8; ++i)
        #pragma unroll
        for (int j = 0; j < 4; ++j) acc[i][j] = 0.0f;

    const float* xA = xs + (mt * 16) * 132;

    #pragma unroll
    for (int k0 = 0; k0 < 128; k0 += 8) {
        uint32_t a0 = __float_as_uint(xA[g * 132 + k0 + t]);
        uint32_t a1 = __float_as_uint(xA[(g + 8) * 132 + k0 + t]);
        uint32_t a2 = __float_as_uint(xA[g * 132 + k0 + t + 4]);
        uint32_t a3 = __float_as_uint(xA[(g + 8) * 132 + k0 + t + 4]);
        #pragma unroll
        for (int nt = 0; nt < 8; ++nt) {
            int n = nh * 64 + nt * 8 + g;
            uint32_t b0 = __float_as_uint(wt[n * 132 + k0 + t]);
            uint32_t b1 = __float_as_uint(wt[n * 132 + k0 + t + 4]);
            mma_tf32(acc[nt], a0, a1, a2, a3, b0, b1);
        }
    }

    // epilogue: store h + fused att partials
    const int row_a = row0 + mt * 16 + g;
    const int row_b = row_a + 8;

    float ps[2][2] = {{0, 0}, {0, 0}};   // [row half][head within pair]
    float pd[2][2] = {{0, 0}, {0, 0}};

    #pragma unroll
    for (int nt = 0; nt < 8; ++nt) {
        int col = nh * 64 + nt * 8 + 2 * t;
        int hl = nt >> 2;   // head within this n-half
        float as0 = attsm[col],       as1 = attsm[col + 1];
        float ad0 = attsm[128 + col], ad1 = attsm[128 + col + 1];
        ps[0][hl] += acc[nt][0] * as0 + acc[nt][1] * as1;
        ps[1][hl] += acc[nt][2] * as0 + acc[nt][3] * as1;
        pd[0][hl] += acc[nt][0] * ad0 + acc[nt][1] * ad1;
        pd[1][hl] += acc[nt][2] * ad0 + acc[nt][3] * ad1;
        if (row_a < N)
            *(float2*)&h[row_a * 128 + col] = make_float2(acc[nt][0], acc[nt][1]);
        if (row_b < N)
            *(float2*)&h[row_b * 128 + col] = make_float2(acc[nt][2], acc[nt][3]);
    }

    // reduce partials across the quad (lanes differing in t)
    #pragma unroll
    for (int r = 0; r < 2; ++r)
        #pragma unroll
        for (int c = 0; c < 2; ++c) {
            ps[r][c] += __shfl_xor_sync(0xffffffffu, ps[r][c], 1);
            ps[r][c] += __shfl_xor_sync(0xffffffffu, ps[r][c], 2);
            pd[r][c] += __shfl_xor_sync(0xffffffffu, pd[r][c], 1);
            pd[r][c] += __shfl_xor_sync(0xffffffffu, pd[r][c], 2);
        }

    if (t == 0) {
        int h0 = nh * 2, h1 = nh * 2 + 1;
        if (row_a < N) {
            asrc[row_a * 4 + h0] = ps[0][0];
            asrc[row_a * 4 + h1] = ps[0][1];
            adst[row_a * 4 + h0] = pd[0][0];
            adst[row_a * 4 + h1] = pd[0][1];
        }
        if (row_b < N) {
            asrc[row_b * 4 + h0] = ps[1][0];
            asrc[row_b * 4 + h1] = ps[1][1];
            adst[row_b * 4 + h0] = pd[1][0];
            adst[row_b * 4 + h1] = pd[1][1];
        }
    }
}

// ---------------------------------------------------------------------------
// CSR build
// ---------------------------------------------------------------------------
__global__ void count_kernel(const int* __restrict__ ei, int E)
{
    int t = blockIdx.x * blockDim.x + threadIdx.x;
    if (t >= E) return;
    atomicAdd(&g_cnt[ei[E + t]], 1);
}

__global__ void scan1_kernel(int N)
{
    __shared__ int sh[1024];
    int tid = threadIdx.x;
    int i = blockIdx.x * 1024 + tid;
    int v = (i < N) ? g_cnt[i] : 0;
    sh[tid] = v;
    __syncthreads();
    #pragma unroll
    for (int off = 1; off < 1024; off <<= 1) {
        int t = (tid >= off) ? sh[tid - off] : 0;
        __syncthreads();
        sh[tid] += t;
        __syncthreads();
    }
    int inc = sh[tid];
    if (i < N) g_off[i] = inc - v;
    if (tid == 1023) g_bsums[blockIdx.x] = inc;
}

__global__ void scan2_kernel(int NB, int N)
{
    __shared__ int sh[128];
    int tid = threadIdx.x;
    int v = (tid < NB) ? g_bsums[tid] : 0;
    sh[tid] = v;
    __syncthreads();
    #pragma unroll
    for (int off = 1; off < 128; off <<= 1) {
        int t = (tid >= off) ? sh[tid - off] : 0;
        __syncthreads();
        sh[tid] += t;
        __syncthreads();
    }
    int inc = sh[tid];
    if (tid < NB) g_bsums[tid] = inc - v;
    if (tid == NB - 1) g_off[N] = inc;
}

__global__ void scan3_kernel(int N)
{
    int i = blockIdx.x * blockDim.x + threadIdx.x;
    if (i >= N) return;
    int o = g_off[i] + g_bsums[i >> 10];
    g_off[i] = o;
    g_cur[i] = o;
}

__global__ void fill_kernel(const int* __restrict__ ei, int E)
{
    int t = blockIdx.x * blockDim.x + threadIdx.x;
    if (t >= E) return;
    int src = ei[t];
    int dst = ei[E + t];
    int pos = atomicAdd(&g_cur[dst], 1);
    g_csr[pos] = src;
}

// ---------------------------------------------------------------------------
// Aggregate: warp per node, single pass (no max subtraction), ELU.
// ---------------------------------------------------------------------------
__device__ __forceinline__ float leaky(float x) {
    return x > 0.0f ? x : NEG_SLOPE * x;
}

__global__ void aggregate_kernel(const float* __restrict__ h,
                                 const float* __restrict__ asrc,
                                 const float* __restrict__ adst,
                                 const float* __restrict__ bias,
                                 float* __restrict__ out, int N)
{
    int gtid = blockIdx.x * blockDim.x + threadIdx.x;
    int n = gtid >> 5;
    int lane = gtid & 31;
    if (n >= N) return;

    const int s0 = g_off[n];
    const int s1 = g_off[n + 1];
    const int myhead = lane >> 3;

    const float admy = adst[n * 4 + myhead];

    // self loop
    float w = __expf(leaky(asrc[n * 4 + myhead] + admy));
    float4 hv = *(const float4*)&h[n * 128 + lane * 4];
    float a0 = w * hv.x, a1 = w * hv.y, a2 = w * hv.z, a3 = w * hv.w;
    float den = ((lane & 7) == 0) ? w : 0.0f;

    int e = s0;
    for (; e + 2 <= s1; e += 2) {
        int sA = g_csr[e];
        int sB = g_csr[e + 1];
        float asA = asrc[sA * 4 + myhead];
        float asB = asrc[sB * 4 + myhead];
        float4 vA = *(const float4*)&h[sA * 128 + lane * 4];
        float4 vB = *(const float4*)&h[sB * 128 + lane * 4];
        float wA = __expf(leaky(asA + admy));
        float wB = __expf(leaky(asB + admy));
        a0 += wA * vA.x; a1 += wA * vA.y; a2 += wA * vA.z; a3 += wA * vA.w;
        a0 += wB * vB.x; a1 += wB * vB.y; a2 += wB * vB.z; a3 += wB * vB.w;
        if ((lane & 7) == 0) den += wA + wB;
    }
    if (e < s1) {
        int s = g_csr[e];
        float asv = asrc[s * 4 + myhead];
        float4 v = *(const float4*)&h[s * 128 + lane * 4];
        float we = __expf(leaky(asv + admy));
        a0 += we * v.x; a1 += we * v.y; a2 += we * v.z; a3 += we * v.w;
        if ((lane & 7) == 0) den += we;
    }

    float dtot = __shfl_sync(0xffffffffu, den, myhead * 8);
    float inv = 1.0f / (dtot + 1e-16f);

    float4 b4 = *(const float4*)&bias[lane * 4];
    float o0 = a0 * inv + b4.x;
    float o1 = a1 * inv + b4.y;
    float o2 = a2 * inv + b4.z;
    float o3 = a3 * inv + b4.w;
    o0 = o0 > 0.0f ? o0 : (__expf(o0) - 1.0f);
    o1 = o1 > 0.0f ? o1 : (__expf(o1) - 1.0f);
    o2 = o2 > 0.0f ? o2 : (__expf(o2) - 1.0f);
    o3 = o3 > 0.0f ? o3 : (__expf(o3) - 1.0f);
    *(float4*)&out[n * 128 + lane * 4] = make_float4(o0, o1, o2, o3);
}

// ---------------------------------------------------------------------------
extern "C" void kernel_launch(void* const* d_in, const int* in_sizes, int n_in,
                              void* d_out, int out_size)
{
    const float* x       = (const float*)d_in[0];
    const int*   ei      = (const int*)d_in[1];
    const float* W       = (const float*)d_in[2];
    const float* att_src = (const float*)d_in[3];
    const float* att_dst = (const float*)d_in[4];
    const float* bias    = (const float*)d_in[5];
    float*       out     = (float*)d_out;

    const int N = in_sizes[0] / 128;
    const int E = in_sizes[1] / 2;

    float *h_p, *asrc_p, *adst_p;
    int *cnt_p;
    cudaGetSymbolAddress((void**)&h_p,    g_h);
    cudaGetSymbolAddress((void**)&asrc_p, g_asrc);
    cudaGetSymbolAddress((void**)&adst_p, g_adst);
    cudaGetSymbolAddress((void**)&cnt_p,  g_cnt);

    cudaFuncSetAttribute(gemm_att_kernel,
                         cudaFuncAttributeMaxDynamicSharedMemorySize, 102400);

    cudaMemsetAsync(cnt_p, 0, N * sizeof(int));

    gemm_att_kernel<<<(N + 63) / 64, 256, 102400>>>(x, W, att_src, att_dst,
                                                    h_p, asrc_p, adst_p, N);
    count_kernel<<<(E + 255) / 256, 256>>>(ei, E);

    int NB = (N + 1023) / 1024;
    scan1_kernel<<<NB, 1024>>>(N);
    scan2_kernel<<<1, 128>>>(NB, N);
    scan3_kernel<<<(N + 255) / 256, 256>>>(N);
    fill_kernel<<<(E + 255) / 256, 256>>>(ei, E);

    aggregate_kernel<<<(N * 32 + 255) / 256, 256>>>(h_p, asrc_p, adst_p,
                                                    bias, out, N);
}